// round 15
// baseline (speedup 1.0000x reference)
#include <cuda_runtime.h>
#include <cuda_bf16.h>
#include <cstddef>

#define COL    4096
#define TPB    256
#define WPB    (TPB/32)     // 8 warps per block, one row per warp
#define NPAIR  8            // 8 pairs of 256-element chunks
#define F4C    64           // float4 per chunk

// Tables filled each launch (graph-capturable, no allocs).
__device__ float g_rinv[COL];          // 1/(i+1)
__device__ float g_csum[16 * 32];      // per (chunk, lane): sum r^2 over lane's 8

__global__ void table_init_kernel() {
    int i = blockIdx.x * blockDim.x + threadIdx.x;
    if (i < COL) g_rinv[i] = 1.0f / (float)(i + 1);
    if (i < 16 * 32) {
        int c = i >> 5, ln = i & 31;
        float s = 0.0f;
        #pragma unroll
        for (int j = 0; j < 8; ++j) {
            float r = 1.0f / (float)(c * 256 + ln * 8 + j + 1);
            s += r * r;
        }
        g_csum[i] = s;
    }
}

// ---- 32-byte L2-steered accesses (.v4.b64 required for evict hints) ----
__device__ __forceinline__ void ldg_el_32(const float4* p, float4& a, float4& b) {
    unsigned long long q0, q1, q2, q3;
    asm volatile("ld.global.nc.L2::evict_last.v4.b64 {%0,%1,%2,%3}, [%4];"
                 : "=l"(q0), "=l"(q1), "=l"(q2), "=l"(q3) : "l"(p));
    a.x = __uint_as_float((unsigned)q0); a.y = __uint_as_float((unsigned)(q0 >> 32));
    a.z = __uint_as_float((unsigned)q1); a.w = __uint_as_float((unsigned)(q1 >> 32));
    b.x = __uint_as_float((unsigned)q2); b.y = __uint_as_float((unsigned)(q2 >> 32));
    b.z = __uint_as_float((unsigned)q3); b.w = __uint_as_float((unsigned)(q3 >> 32));
}
__device__ __forceinline__ void ldg_ef_32(const float4* p, float4& a, float4& b) {
    unsigned long long q0, q1, q2, q3;
    asm volatile("ld.global.nc.L2::evict_first.v4.b64 {%0,%1,%2,%3}, [%4];"
                 : "=l"(q0), "=l"(q1), "=l"(q2), "=l"(q3) : "l"(p));
    a.x = __uint_as_float((unsigned)q0); a.y = __uint_as_float((unsigned)(q0 >> 32));
    a.z = __uint_as_float((unsigned)q1); a.w = __uint_as_float((unsigned)(q1 >> 32));
    b.x = __uint_as_float((unsigned)q2); b.y = __uint_as_float((unsigned)(q2 >> 32));
    b.z = __uint_as_float((unsigned)q3); b.w = __uint_as_float((unsigned)(q3 >> 32));
}
__device__ __forceinline__ void stg_ef_32(float4* p, float4 a, float4 b) {
    unsigned long long q0 = ((unsigned long long)__float_as_uint(a.y) << 32) | __float_as_uint(a.x);
    unsigned long long q1 = ((unsigned long long)__float_as_uint(a.w) << 32) | __float_as_uint(a.z);
    unsigned long long q2 = ((unsigned long long)__float_as_uint(b.y) << 32) | __float_as_uint(b.x);
    unsigned long long q3 = ((unsigned long long)__float_as_uint(b.w) << 32) | __float_as_uint(b.z);
    asm volatile("st.global.L2::evict_first.v4.b64 [%0], {%1,%2,%3,%4};"
                 :: "l"(p), "l"(q0), "l"(q1), "l"(q2), "l"(q3) : "memory");
}

// Local scan + A/B accumulation for one 8-element chunk slice.
__device__ __forceinline__ void chunk_local(const float4 d0, const float4 d1,
                                            const float4 r0, const float4 r1,
                                            float& A, float& B, float& tot)
{
    float p, q;
    p = d0.x;        q = d0.x - p * r0.x; A  = q * q; B  = q * r0.x;
    p += d0.y;       q = d0.y - p * r0.y; A += q * q; B += q * r0.y;
    p += d0.z;       q = d0.z - p * r0.z; A += q * q; B += q * r0.z;
    p += d0.w;       q = d0.w - p * r0.w; A += q * q; B += q * r0.w;
    p += d1.x;       q = d1.x - p * r1.x; A += q * q; B += q * r1.x;
    p += d1.y;       q = d1.y - p * r1.y; A += q * q; B += q * r1.y;
    p += d1.z;       q = d1.z - p * r1.z; A += q * q; B += q * r1.z;
    p += d1.w;       q = d1.w - p * r1.w; A += q * q; B += q * r1.w;
    tot = p;
}

__global__ __launch_bounds__(TPB, 5) void layernorm_v2_kernel(
    const float* __restrict__ x,
    const float* __restrict__ alpha,
    const float* __restrict__ beta,
    float* __restrict__ out)
{
    const int lane = threadIdx.x & 31;
    const int wid  = threadIdx.x >> 5;
    const size_t row = (size_t)blockIdx.x * WPB + wid;

    const float4* xr  = (const float4*)(x + row * COL);
    const float4* rr  = (const float4*)g_rinv;
    float4*       orw = (float4*)(out + row * COL);

    const int l2 = lane * 2;   // lane's 32B pair within a chunk

    // ---- pass 1: chunk-PAIRS with ILP-2 scans, double-buffered loads ----
    float4 a0, a1, b0, b1;                       // current pair (chunks 2p, 2p+1)
    ldg_el_32(xr + l2,       a0, a1);
    ldg_el_32(xr + F4C + l2, b0, b1);
    float carry = 0.0f;
    float acc   = 0.0f;

    #pragma unroll 1
    for (int p = 0; p < NPAIR; ++p) {
        const int cA = 2 * p, cB = 2 * p + 1;

        // prefetch next pair (stays in flight across this pair's compute)
        float4 na0, na1, nb0, nb1;
        if (p + 1 < NPAIR) {
            ldg_el_32(xr + (cA + 2) * F4C + l2, na0, na1);
            ldg_el_32(xr + (cB + 2) * F4C + l2, nb0, nb1);
        }

        // reciprocal slices (L1-resident) + per-chunk C constants
        const float4 ra0 = rr[cA * F4C + l2];
        const float4 ra1 = rr[cA * F4C + l2 + 1];
        const float4 rb0 = rr[cB * F4C + l2];
        const float4 rb1 = rr[cB * F4C + l2 + 1];
        const float  Ca  = g_csum[cA * 32 + lane];
        const float  Cb  = g_csum[cB * 32 + lane];

        // two independent local scans + A/B
        float Aa, Ba, ta, Ab, Bb, tb;
        chunk_local(a0, a1, ra0, ra1, Aa, Ba, ta);
        chunk_local(b0, b1, rb0, rb1, Ab, Bb, tb);

        // two interleaved warp scans (independent shfl chains)
        float va = ta, vb = tb;
        #pragma unroll
        for (int o = 1; o < 32; o <<= 1) {
            float sa = __shfl_up_sync(0xffffffffu, va, o);
            float sb = __shfl_up_sync(0xffffffffu, vb, o);
            if (lane >= o) { va += sa; vb += sb; }
        }
        const float totA = __shfl_sync(0xffffffffu, va, 31);
        const float totB = __shfl_sync(0xffffffffu, vb, 31);
        const float la = va - ta;
        const float lb = vb - tb;

        // carry joins AFTER both scans (scalar adds, not on shfl path)
        const float ea = carry + la;
        const float eb = carry + totA + lb;
        acc += (Aa - 2.0f * ea * Ba + ea * ea * Ca)
             + (Ab - 2.0f * eb * Bb + eb * eb * Cb);
        carry += totA + totB;

        a0 = na0; a1 = na1; b0 = nb0; b1 = nb1;
    }

    // ---- warp-local stats (no barriers anywhere) ----
    #pragma unroll
    for (int o = 16; o > 0; o >>= 1) acc += __shfl_xor_sync(0xffffffffu, acc, o);

    const float var   = acc   * (1.0f / (float)(COL - 1));
    const float mean  = carry * (1.0f / (float)COL);
    const float scale = __ldg(alpha) * rsqrtf(var + 1e-5f);
    const float shift = __ldg(beta) - mean * scale;    // out = x*scale + shift

    // ---- pass 2: re-read row (L2-pinned), release lines, stream stores ----
    #pragma unroll 4
    for (int c = 0; c < 2 * NPAIR; ++c) {
        float4 u, v;
        ldg_ef_32(xr + c * F4C + l2, u, v);
        float4 ou, ov;
        ou.x = u.x * scale + shift;
        ou.y = u.y * scale + shift;
        ou.z = u.z * scale + shift;
        ou.w = u.w * scale + shift;
        ov.x = v.x * scale + shift;
        ov.y = v.y * scale + shift;
        ov.z = v.z * scale + shift;
        ov.w = v.w * scale + shift;
        stg_ef_32(orw + c * F4C + l2, ou, ov);
    }
}

extern "C" void kernel_launch(void* const* d_in, const int* in_sizes, int n_in,
                              void* d_out, int out_size)
{
    const float* x     = (const float*)d_in[0];
    const float* alpha = (const float*)d_in[1];
    const float* beta  = (const float*)d_in[2];
    float*       out   = (float*)d_out;

    const int rows = in_sizes[0] / COL;
    const int grid = rows / WPB;                 // 4096 blocks x 8 warp-rows

    table_init_kernel<<<(COL + 255) / 256, 256>>>();
    layernorm_v2_kernel<<<grid, TPB>>>(x, alpha, beta, out);
}

// round 16
// speedup vs baseline: 1.2281x; 1.2281x over previous
#include <cuda_runtime.h>
#include <cuda_bf16.h>
#include <cstddef>

#define COL    4096
#define TPB    256
#define WPB    (TPB/32)     // 8 warps per block, one row per warp
#define NPAIR  8            // 8 pairs of 256-element chunks
#define F4C    64           // float4 per chunk
#define NSTAGE 6            // chunks 0..5 staged in smem (oldest at re-read time)

// Tables filled each launch (graph-capturable, no allocs).
__device__ float g_rinv[COL];          // 1/(i+1)
__device__ float g_csum[16 * 32];      // per (chunk, lane): sum r^2 over lane's 8

__global__ void table_init_kernel() {
    int i = blockIdx.x * blockDim.x + threadIdx.x;
    if (i < COL) g_rinv[i] = 1.0f / (float)(i + 1);
    if (i < 16 * 32) {
        int c = i >> 5, ln = i & 31;
        float s = 0.0f;
        #pragma unroll
        for (int j = 0; j < 8; ++j) {
            float r = 1.0f / (float)(c * 256 + ln * 8 + j + 1);
            s += r * r;
        }
        g_csum[i] = s;
    }
}

// ---- 32-byte L2-steered accesses (.v4.b64 required for evict hints) ----
__device__ __forceinline__ void ldg_el_32(const float4* p, float4& a, float4& b) {
    unsigned long long q0, q1, q2, q3;
    asm volatile("ld.global.nc.L2::evict_last.v4.b64 {%0,%1,%2,%3}, [%4];"
                 : "=l"(q0), "=l"(q1), "=l"(q2), "=l"(q3) : "l"(p));
    a.x = __uint_as_float((unsigned)q0); a.y = __uint_as_float((unsigned)(q0 >> 32));
    a.z = __uint_as_float((unsigned)q1); a.w = __uint_as_float((unsigned)(q1 >> 32));
    b.x = __uint_as_float((unsigned)q2); b.y = __uint_as_float((unsigned)(q2 >> 32));
    b.z = __uint_as_float((unsigned)q3); b.w = __uint_as_float((unsigned)(q3 >> 32));
}
__device__ __forceinline__ void ldg_ef_32(const float4* p, float4& a, float4& b) {
    unsigned long long q0, q1, q2, q3;
    asm volatile("ld.global.nc.L2::evict_first.v4.b64 {%0,%1,%2,%3}, [%4];"
                 : "=l"(q0), "=l"(q1), "=l"(q2), "=l"(q3) : "l"(p));
    a.x = __uint_as_float((unsigned)q0); a.y = __uint_as_float((unsigned)(q0 >> 32));
    a.z = __uint_as_float((unsigned)q1); a.w = __uint_as_float((unsigned)(q1 >> 32));
    b.x = __uint_as_float((unsigned)q2); b.y = __uint_as_float((unsigned)(q2 >> 32));
    b.z = __uint_as_float((unsigned)q3); b.w = __uint_as_float((unsigned)(q3 >> 32));
}
__device__ __forceinline__ void stg_ef_32(float4* p, float4 a, float4 b) {
    unsigned long long q0 = ((unsigned long long)__float_as_uint(a.y) << 32) | __float_as_uint(a.x);
    unsigned long long q1 = ((unsigned long long)__float_as_uint(a.w) << 32) | __float_as_uint(a.z);
    unsigned long long q2 = ((unsigned long long)__float_as_uint(b.y) << 32) | __float_as_uint(b.x);
    unsigned long long q3 = ((unsigned long long)__float_as_uint(b.w) << 32) | __float_as_uint(b.z);
    asm volatile("st.global.L2::evict_first.v4.b64 [%0], {%1,%2,%3,%4};"
                 :: "l"(p), "l"(q0), "l"(q1), "l"(q2), "l"(q3) : "memory");
}

// Local scan + A/B accumulation for one 8-element chunk slice.
__device__ __forceinline__ void chunk_local(const float4 d0, const float4 d1,
                                            const float4 r0, const float4 r1,
                                            float& A, float& B, float& tot)
{
    float p, q;
    p = d0.x;        q = d0.x - p * r0.x; A  = q * q; B  = q * r0.x;
    p += d0.y;       q = d0.y - p * r0.y; A += q * q; B += q * r0.y;
    p += d0.z;       q = d0.z - p * r0.z; A += q * q; B += q * r0.z;
    p += d0.w;       q = d0.w - p * r0.w; A += q * q; B += q * r0.w;
    p += d1.x;       q = d1.x - p * r1.x; A += q * q; B += q * r1.x;
    p += d1.y;       q = d1.y - p * r1.y; A += q * q; B += q * r1.y;
    p += d1.z;       q = d1.z - p * r1.z; A += q * q; B += q * r1.z;
    p += d1.w;       q = d1.w - p * r1.w; A += q * q; B += q * r1.w;
    tot = p;
}

__global__ __launch_bounds__(TPB, 4) void layernorm_v2_kernel(
    const float* __restrict__ x,
    const float* __restrict__ alpha,
    const float* __restrict__ beta,
    float* __restrict__ out)
{
    // 48 KB: NSTAGE oldest chunks per warp (6 KB each), conflict-free layout
    __shared__ float4 sbuf[WPB * NSTAGE * F4C];

    const int lane = threadIdx.x & 31;
    const int wid  = threadIdx.x >> 5;
    const size_t row = (size_t)blockIdx.x * WPB + wid;

    const float4* xr  = (const float4*)(x + row * COL);
    const float4* rr  = (const float4*)g_rinv;
    float4*       orw = (float4*)(out + row * COL);
    float4*       sw  = sbuf + wid * (NSTAGE * F4C);

    const int l2 = lane * 2;   // lane's 32B pair within a chunk

    // ---- pass 1: chunk-PAIRS with ILP-2 scans, double-buffered loads ----
    float4 a0, a1, b0, b1;                       // current pair (chunks 2p, 2p+1)
    ldg_ef_32(xr + l2,       a0, a1);            // chunks 0,1: staged -> dead in L2
    ldg_ef_32(xr + F4C + l2, b0, b1);
    float carry = 0.0f;
    float acc   = 0.0f;

    #pragma unroll 1
    for (int p = 0; p < NPAIR; ++p) {
        const int cA = 2 * p, cB = 2 * p + 1;

        // prefetch next pair; staged chunks dead in L2, young chunks pinned
        float4 na0, na1, nb0, nb1;
        if (p + 1 < NPAIR) {
            if (2 * (p + 1) < NSTAGE) {
                ldg_ef_32(xr + (cA + 2) * F4C + l2, na0, na1);
                ldg_ef_32(xr + (cB + 2) * F4C + l2, nb0, nb1);
            } else {
                ldg_el_32(xr + (cA + 2) * F4C + l2, na0, na1);
                ldg_el_32(xr + (cB + 2) * F4C + l2, nb0, nb1);
            }
        }

        // stage oldest chunks into smem (STS off registers, no chain latency)
        if (cA < NSTAGE) {
            sw[cA * F4C + lane]      = a0;
            sw[cA * F4C + 32 + lane] = a1;
            sw[cB * F4C + lane]      = b0;
            sw[cB * F4C + 32 + lane] = b1;
        }

        // reciprocal slices (L1-resident) + per-chunk C constants
        const float4 ra0 = rr[cA * F4C + l2];
        const float4 ra1 = rr[cA * F4C + l2 + 1];
        const float4 rb0 = rr[cB * F4C + l2];
        const float4 rb1 = rr[cB * F4C + l2 + 1];
        const float  Ca  = g_csum[cA * 32 + lane];
        const float  Cb  = g_csum[cB * 32 + lane];

        // two independent local scans + A/B
        float Aa, Ba, ta, Ab, Bb, tb;
        chunk_local(a0, a1, ra0, ra1, Aa, Ba, ta);
        chunk_local(b0, b1, rb0, rb1, Ab, Bb, tb);

        // two interleaved warp scans (independent shfl chains)
        float va = ta, vb = tb;
        #pragma unroll
        for (int o = 1; o < 32; o <<= 1) {
            float sa = __shfl_up_sync(0xffffffffu, va, o);
            float sb = __shfl_up_sync(0xffffffffu, vb, o);
            if (lane >= o) { va += sa; vb += sb; }
        }
        const float totA = __shfl_sync(0xffffffffu, va, 31);
        const float totB = __shfl_sync(0xffffffffu, vb, 31);
        const float la = va - ta;
        const float lb = vb - tb;

        // carry joins AFTER both scans (scalar adds, not on shfl path)
        const float ea = carry + la;
        const float eb = carry + totA + lb;
        acc += (Aa - 2.0f * ea * Ba + ea * ea * Ca)
             + (Ab - 2.0f * eb * Bb + eb * eb * Cb);
        carry += totA + totB;

        a0 = na0; a1 = na1; b0 = nb0; b1 = nb1;
    }

    // ---- warp-local stats (no barriers anywhere) ----
    #pragma unroll
    for (int o = 16; o > 0; o >>= 1) acc += __shfl_xor_sync(0xffffffffu, acc, o);

    const float var   = acc   * (1.0f / (float)(COL - 1));
    const float mean  = carry * (1.0f / (float)COL);
    const float scale = __ldg(alpha) * rsqrtf(var + 1e-5f);
    const float shift = __ldg(beta) - mean * scale;    // out = x*scale + shift

    // ---- pass 2a: chunks 0..5 from smem (zero DRAM) ----
    #pragma unroll 2
    for (int c = 0; c < NSTAGE; ++c) {
        float4 u = sw[c * F4C + lane];
        float4 v = sw[c * F4C + 32 + lane];
        float4 ou, ov;
        ou.x = u.x * scale + shift;
        ou.y = u.y * scale + shift;
        ou.z = u.z * scale + shift;
        ou.w = u.w * scale + shift;
        ov.x = v.x * scale + shift;
        ov.y = v.y * scale + shift;
        ov.z = v.z * scale + shift;
        ov.w = v.w * scale + shift;
        stg_ef_32(orw + c * F4C + l2, ou, ov);
    }

    // ---- pass 2b: chunks 6..15 re-read (young pinned lines), release, store ----
    #pragma unroll 2
    for (int c = NSTAGE; c < 16; ++c) {
        float4 u, v;
        ldg_ef_32(xr + c * F4C + l2, u, v);
        float4 ou, ov;
        ou.x = u.x * scale + shift;
        ou.y = u.y * scale + shift;
        ou.z = u.z * scale + shift;
        ou.w = u.w * scale + shift;
        ov.x = v.x * scale + shift;
        ov.y = v.y * scale + shift;
        ov.z = v.z * scale + shift;
        ov.w = v.w * scale + shift;
        stg_ef_32(orw + c * F4C + l2, ou, ov);
    }
}

extern "C" void kernel_launch(void* const* d_in, const int* in_sizes, int n_in,
                              void* d_out, int out_size)
{
    const float* x     = (const float*)d_in[0];
    const float* alpha = (const float*)d_in[1];
    const float* beta  = (const float*)d_in[2];
    float*       out   = (float*)d_out;

    const int rows = in_sizes[0] / COL;
    const int grid = rows / WPB;                 // 4096 blocks x 8 warp-rows

    table_init_kernel<<<(COL + 255) / 256, 256>>>();
    layernorm_v2_kernel<<<grid, TPB>>>(x, alpha, beta, out);
}